// round 5
// baseline (speedup 1.0000x reference)
#include <cuda_runtime.h>
#include <cuda_bf16.h>
#include <math.h>

#define TT 2048      // B*S tokens
#define DD 1024      // model dim
#define FFD 4096     // ff dim
#define VV 32000     // vocab
#define HH 16        // heads
#define HD 64        // head dim
#define LL 6         // layers
#define SS 1024      // seq len
#define BB 2         // batch

// ---------------- scratch (no allocation allowed) ----------------
__device__ float g_x[TT * DD];
__device__ float g_h[TT * DD];
__device__ float g_q[TT * DD];
__device__ float g_k[TT * DD];
__device__ float g_v[TT * DD];
__device__ float g_at[TT * DD];
__device__ float g_ff[TT * FFD];

// ---------------- embedding + sinusoidal positional encoding ----------------
__global__ void embed_kernel(const float* __restrict__ emb,
                             const int* __restrict__ ids,
                             float* __restrict__ x) {
    int idx = blockIdx.x * 256 + threadIdx.x;
    if (idx >= TT * DD) return;
    int t = idx >> 10;          // token index
    int d = idx & (DD - 1);     // dim index
    int pos = t & (SS - 1);     // position within sequence
    float val = emb[ids[t] * DD + d] * 32.0f;   // sqrt(1024) = 32
    // div[i] = exp(-(2i)*ln(10000)/1024), i = d/2
    float ang = (float)pos * expf((float)(d & ~1) * (-9.210340371976184f / 1024.0f));
    val += (d & 1) ? cosf(ang) : sinf(ang);
    x[idx] = val;
}

// ---------------- layernorm (one block per row of 1024) ----------------
__global__ __launch_bounds__(256) void ln_kernel(const float* __restrict__ x,
                                                 const float* __restrict__ g,
                                                 const float* __restrict__ bta,
                                                 float* __restrict__ out) {
    int row = blockIdx.x;
    const float* xr = x + (size_t)row * DD;
    float s1 = 0.f, s2 = 0.f;
    for (int i = threadIdx.x; i < DD; i += 256) {
        float v = xr[i];
        s1 += v;
        s2 = fmaf(v, v, s2);
    }
    for (int o = 16; o; o >>= 1) {
        s1 += __shfl_xor_sync(0xffffffffu, s1, o);
        s2 += __shfl_xor_sync(0xffffffffu, s2, o);
    }
    __shared__ float r1[8], r2[8];
    __shared__ float smean, srstd;
    int w = threadIdx.x >> 5, lane = threadIdx.x & 31;
    if (lane == 0) { r1[w] = s1; r2[w] = s2; }
    __syncthreads();
    if (threadIdx.x == 0) {
        float t1 = 0.f, t2 = 0.f;
        for (int i = 0; i < 8; i++) { t1 += r1[i]; t2 += r2[i]; }
        float mean = t1 * (1.0f / DD);
        float var  = t2 * (1.0f / DD) - mean * mean;
        smean = mean;
        srstd = rsqrtf(var + 1e-5f);
    }
    __syncthreads();
    float mean = smean, rstd = srstd;
    for (int i = threadIdx.x; i < DD; i += 256)
        out[(size_t)row * DD + i] = (xr[i] - mean) * rstd * g[i] + bta[i];
}

// ---------------- 128x128x8 SGEMM body, 256 threads, 8x8 per thread ----------------
// C[M,N] = A[M,K] @ B[K,N] (+bias) (gelu?) (+res). M%128==0, N%128==0, K%8==0.
__device__ __forceinline__ void gemm_body(const float* __restrict__ A,
                                          const float* __restrict__ Bw,
                                          const float* __restrict__ bias,
                                          const float* __restrict__ res,
                                          float* __restrict__ C,
                                          int M, int N, int K, int gelu) {
    __shared__ float As[8][128];
    __shared__ float Bs[8][128];
    int tid = threadIdx.x;
    int bm = blockIdx.y, bn = blockIdx.x;

    int aRow = tid >> 1;            // 0..127
    int aCol = (tid & 1) << 2;      // 0 or 4
    int bRow = tid >> 5;            // 0..7
    int bCol = (tid & 31) << 2;     // 0..124

    const float* Ap = A + (size_t)(bm * 128 + aRow) * K + aCol;
    const float* Bp = Bw + (size_t)bRow * N + bn * 128 + bCol;

    int ty = (tid >> 4) << 3;       // 0..120 step 8
    int tx = (tid & 15) << 3;       // 0..120 step 8

    float acc[8][8];
#pragma unroll
    for (int i = 0; i < 8; i++)
#pragma unroll
        for (int j = 0; j < 8; j++) acc[i][j] = 0.f;

    for (int k0 = 0; k0 < K; k0 += 8) {
        float4 a4 = *(const float4*)Ap;  Ap += 8;
        float4 b4 = *(const float4*)Bp;  Bp += (size_t)8 * N;
        As[aCol + 0][aRow] = a4.x;
        As[aCol + 1][aRow] = a4.y;
        As[aCol + 2][aRow] = a4.z;
        As[aCol + 3][aRow] = a4.w;
        *(float4*)&Bs[bRow][bCol] = b4;
        __syncthreads();
#pragma unroll
        for (int kk = 0; kk < 8; kk++) {
            float4 a0 = *(const float4*)&As[kk][ty];
            float4 a1 = *(const float4*)&As[kk][ty + 4];
            float4 b0 = *(const float4*)&Bs[kk][tx];
            float4 b1 = *(const float4*)&Bs[kk][tx + 4];
            float ra[8] = {a0.x, a0.y, a0.z, a0.w, a1.x, a1.y, a1.z, a1.w};
            float rb[8] = {b0.x, b0.y, b0.z, b0.w, b1.x, b1.y, b1.z, b1.w};
#pragma unroll
            for (int i = 0; i < 8; i++)
#pragma unroll
                for (int j = 0; j < 8; j++)
                    acc[i][j] = fmaf(ra[i], rb[j], acc[i][j]);
        }
        __syncthreads();
    }

    int row0 = bm * 128 + ty, col0 = bn * 128 + tx;
#pragma unroll
    for (int i = 0; i < 8; i++) {
        int row = row0 + i;
        size_t base = (size_t)row * N + col0;
#pragma unroll
        for (int j = 0; j < 8; j++) {
            float vv = acc[i][j];
            if (bias) vv += bias[col0 + j];
            if (gelu) vv = 0.5f * vv * (1.0f + erff(vv * 0.70710678118654752f));
            if (res)  vv += res[base + j];
            C[base + j] = vv;
        }
    }
}

__global__ __launch_bounds__(256, 2) void sgemm_kernel(const float* A, const float* Bw,
                                                       const float* bias, const float* res,
                                                       float* C, int M, int N, int K, int gelu) {
    gemm_body(A, Bw, bias, res, C, M, N, K, gelu);
}

// fused QKV: blockIdx.z selects which projection (384 blocks -> better SM fill)
__global__ __launch_bounds__(256, 2) void sgemm_qkv_kernel(const float* A,
                                                           const float* Wq, const float* Wk, const float* Wv,
                                                           const float* bq, const float* bk, const float* bv,
                                                           float* Q, float* Ko, float* Vo) {
    const float* W; const float* bi; float* C;
    if (blockIdx.z == 0)      { W = Wq; bi = bq; C = Q;  }
    else if (blockIdx.z == 1) { W = Wk; bi = bk; C = Ko; }
    else                      { W = Wv; bi = bv; C = Vo; }
    gemm_body(A, W, bi, nullptr, C, TT, DD, DD, 0);
}

// ---------------- causal attention: one block per (b, h, q) ----------------
__global__ __launch_bounds__(256) void attn_kernel(const float* __restrict__ Q,
                                                   const float* __restrict__ Kc,
                                                   const float* __restrict__ Vc,
                                                   float* __restrict__ O) {
    int qi = blockIdx.x, h = blockIdx.y, b = blockIdx.z;
    int tid = threadIdx.x;
    __shared__ float sc[SS];
    __shared__ float qs[HD];
    __shared__ float red[8];
    __shared__ float pv[4][HD];
    __shared__ float s_m, s_s;

    const float* qrow = Q + (size_t)(b * SS + qi) * DD + h * HD;
    if (tid < HD) qs[tid] = qrow[tid];
    __syncthreads();

    int n = qi + 1;
    float lmax = -1e30f;
    for (int j = tid; j < n; j += 256) {
        const float* kr = Kc + (size_t)(b * SS + j) * DD + h * HD;
        float d = 0.f;
#pragma unroll
        for (int t4 = 0; t4 < 16; t4++) {
            float4 k4 = *(const float4*)(kr + t4 * 4);
            d += qs[t4 * 4 + 0] * k4.x + qs[t4 * 4 + 1] * k4.y +
                 qs[t4 * 4 + 2] * k4.z + qs[t4 * 4 + 3] * k4.w;
        }
        d *= 0.125f;  // 1/sqrt(64)
        sc[j] = d;
        lmax = fmaxf(lmax, d);
    }
    for (int o = 16; o; o >>= 1) lmax = fmaxf(lmax, __shfl_xor_sync(0xffffffffu, lmax, o));
    if (!(tid & 31)) red[tid >> 5] = lmax;
    __syncthreads();
    if (tid == 0) {
        float m = red[0];
        for (int i = 1; i < 8; i++) m = fmaxf(m, red[i]);
        s_m = m;
    }
    __syncthreads();
    float m = s_m;
    float lsum = 0.f;
    for (int j = tid; j < n; j += 256) {
        float e = __expf(sc[j] - m);
        sc[j] = e;
        lsum += e;
    }
    for (int o = 16; o; o >>= 1) lsum += __shfl_xor_sync(0xffffffffu, lsum, o);
    __syncthreads();               // red reuse + sc visibility
    if (!(tid & 31)) red[tid >> 5] = lsum;
    __syncthreads();
    if (tid == 0) {
        float s = 0.f;
        for (int i = 0; i < 8; i++) s += red[i];
        s_s = s;
    }
    __syncthreads();
    float inv = 1.0f / s_s;

    int d = tid & 63, grp = tid >> 6;       // 4 groups x 64 dims
    float acc = 0.f;
    for (int j = grp; j < n; j += 4)
        acc += sc[j] * Vc[(size_t)(b * SS + j) * DD + h * HD + d];
    pv[grp][d] = acc;
    __syncthreads();
    if (tid < HD)
        O[(size_t)(b * SS + qi) * DD + h * HD + tid] =
            (pv[0][tid] + pv[1][tid] + pv[2][tid] + pv[3][tid]) * inv;
}

// ---------------- launch ----------------
extern "C" void kernel_launch(void* const* d_in, const int* in_sizes, int n_in,
                              void* d_out, int out_size) {
    const float* emb  = (const float*)d_in[0];
    const float* Wq   = (const float*)d_in[1];
    const float* bq   = (const float*)d_in[2];
    const float* Wk   = (const float*)d_in[3];
    const float* bk   = (const float*)d_in[4];
    const float* Wv   = (const float*)d_in[5];
    const float* bv   = (const float*)d_in[6];
    const float* Wo   = (const float*)d_in[7];
    const float* bo   = (const float*)d_in[8];
    const float* ln1g = (const float*)d_in[9];
    const float* ln1b = (const float*)d_in[10];
    const float* W1   = (const float*)d_in[11];
    const float* b1   = (const float*)d_in[12];
    const float* W2   = (const float*)d_in[13];
    const float* b2   = (const float*)d_in[14];
    const float* ln2g = (const float*)d_in[15];
    const float* ln2b = (const float*)d_in[16];
    const float* lnfg = (const float*)d_in[17];
    const float* lnfb = (const float*)d_in[18];
    const float* Wout = (const float*)d_in[19];
    const int*   ids  = (const int*)d_in[20];

    float *x, *h, *q, *k, *v, *at, *ff;
    cudaGetSymbolAddress((void**)&x,  g_x);
    cudaGetSymbolAddress((void**)&h,  g_h);
    cudaGetSymbolAddress((void**)&q,  g_q);
    cudaGetSymbolAddress((void**)&k,  g_k);
    cudaGetSymbolAddress((void**)&v,  g_v);
    cudaGetSymbolAddress((void**)&at, g_at);
    cudaGetSymbolAddress((void**)&ff, g_ff);

    embed_kernel<<<(TT * DD) / 256, 256>>>(emb, ids, x);

    dim3 gN1(DD / 128, TT / 128);        // (8, 16)
    dim3 gQKV(DD / 128, TT / 128, 3);    // (8, 16, 3)
    dim3 gFF1(FFD / 128, TT / 128);      // (32, 16)
    dim3 gOut(VV / 128, TT / 128);       // (250, 16)
    dim3 gAttn(SS, HH, BB);

    for (int l = 0; l < LL; l++) {
        size_t woff = (size_t)l * DD * DD;
        ln_kernel<<<TT, 256>>>(x, ln1g + l * DD, ln1b + l * DD, h);
        sgemm_qkv_kernel<<<gQKV, 256>>>(h, Wq + woff, Wk + woff, Wv + woff,
                                        bq + l * DD, bk + l * DD, bv + l * DD,
                                        q, k, v);
        attn_kernel<<<gAttn, 256>>>(q, k, v, at);
        // x = x + attn @ Wo + bo   (in-place residual: each element owned by one thread)
        sgemm_kernel<<<gN1, 256>>>(at, Wo + woff, bo + l * DD, x, x, TT, DD, DD, 0);
        ln_kernel<<<TT, 256>>>(x, ln2g + l * DD, ln2b + l * DD, h);
        // ff = gelu(h @ W1 + b1)
        sgemm_kernel<<<gFF1, 256>>>(h, W1 + (size_t)l * DD * FFD, b1 + l * FFD,
                                    nullptr, ff, TT, FFD, DD, 1);
        // x = x + ff @ W2 + b2
        sgemm_kernel<<<gN1, 256>>>(ff, W2 + (size_t)l * FFD * DD, b2 + l * DD,
                                   x, x, TT, DD, FFD, 0);
    }
    ln_kernel<<<TT, 256>>>(x, lnfg, lnfb, h);
    // logits = h @ Wout  (no bias)
    sgemm_kernel<<<gOut, 256>>>(h, Wout, nullptr, nullptr, (float*)d_out,
                                TT, VV, DD, 0);
}

// round 6
// speedup vs baseline: 1.0018x; 1.0018x over previous
#include <cuda_runtime.h>
#include <cuda_bf16.h>
#include <math.h>

#define TT 2048      // B*S tokens
#define DD 1024      // model dim
#define FFD 4096     // ff dim
#define VV 32000     // vocab
#define HH 16        // heads
#define HD 64        // head dim
#define LL 6         // layers
#define SS 1024      // seq len
#define BB 2         // batch

// ---------------- scratch (no allocation allowed) ----------------
__device__ float g_x[TT * DD];
__device__ float g_h[TT * DD];
__device__ float g_q[TT * DD];
__device__ float g_k[TT * DD];
__device__ float g_v[TT * DD];
__device__ float g_at[TT * DD];
__device__ float g_ff[TT * FFD];

// ---------------- embedding + sinusoidal positional encoding ----------------
__global__ void embed_kernel(const float* __restrict__ emb,
                             const int* __restrict__ ids,
                             float* __restrict__ x) {
    int idx = blockIdx.x * 256 + threadIdx.x;
    if (idx >= TT * DD) return;
    int t = idx >> 10;          // token index
    int d = idx & (DD - 1);     // dim index
    int pos = t & (SS - 1);     // position within sequence
    float val = emb[ids[t] * DD + d] * 32.0f;   // sqrt(1024) = 32
    // div[i] = exp(-(2i)*ln(10000)/1024), i = d/2
    float ang = (float)pos * expf((float)(d & ~1) * (-9.210340371976184f / 1024.0f));
    val += (d & 1) ? cosf(ang) : sinf(ang);
    x[idx] = val;
}

// ---------------- layernorm (one block per row of 1024) ----------------
__global__ __launch_bounds__(256) void ln_kernel(const float* __restrict__ x,
                                                 const float* __restrict__ g,
                                                 const float* __restrict__ bta,
                                                 float* __restrict__ out) {
    int row = blockIdx.x;
    const float* xr = x + (size_t)row * DD;
    float s1 = 0.f, s2 = 0.f;
    for (int i = threadIdx.x; i < DD; i += 256) {
        float v = xr[i];
        s1 += v;
        s2 = fmaf(v, v, s2);
    }
    for (int o = 16; o; o >>= 1) {
        s1 += __shfl_xor_sync(0xffffffffu, s1, o);
        s2 += __shfl_xor_sync(0xffffffffu, s2, o);
    }
    __shared__ float r1[8], r2[8];
    __shared__ float smean, srstd;
    int w = threadIdx.x >> 5, lane = threadIdx.x & 31;
    if (lane == 0) { r1[w] = s1; r2[w] = s2; }
    __syncthreads();
    if (threadIdx.x == 0) {
        float t1 = 0.f, t2 = 0.f;
        for (int i = 0; i < 8; i++) { t1 += r1[i]; t2 += r2[i]; }
        float mean = t1 * (1.0f / DD);
        float var  = t2 * (1.0f / DD) - mean * mean;
        smean = mean;
        srstd = rsqrtf(var + 1e-5f);
    }
    __syncthreads();
    float mean = smean, rstd = srstd;
    for (int i = threadIdx.x; i < DD; i += 256)
        out[(size_t)row * DD + i] = (xr[i] - mean) * rstd * g[i] + bta[i];
}

// ---------------- 128x128x8 SGEMM body, 256 threads, 8x8 per thread ----------------
// C[M,N] = A[M,K] @ B[K,N] (+bias) (gelu?) (+res). M%128==0, N%128==0, K%8==0.
__device__ __forceinline__ void gemm_body(const float* __restrict__ A,
                                          const float* __restrict__ Bw,
                                          const float* __restrict__ bias,
                                          const float* __restrict__ res,
                                          float* __restrict__ C,
                                          int M, int N, int K, int gelu) {
    __shared__ float As[8][128];
    __shared__ float Bs[8][128];
    int tid = threadIdx.x;
    int bm = blockIdx.y, bn = blockIdx.x;

    int aRow = tid >> 1;            // 0..127
    int aCol = (tid & 1) << 2;      // 0 or 4
    int bRow = tid >> 5;            // 0..7
    int bCol = (tid & 31) << 2;     // 0..124

    const float* Ap = A + (size_t)(bm * 128 + aRow) * K + aCol;
    const float* Bp = Bw + (size_t)bRow * N + bn * 128 + bCol;

    int ty = (tid >> 4) << 3;       // 0..120 step 8
    int tx = (tid & 15) << 3;       // 0..120 step 8

    float acc[8][8];
#pragma unroll
    for (int i = 0; i < 8; i++)
#pragma unroll
        for (int j = 0; j < 8; j++) acc[i][j] = 0.f;

    for (int k0 = 0; k0 < K; k0 += 8) {
        float4 a4 = *(const float4*)Ap;  Ap += 8;
        float4 b4 = *(const float4*)Bp;  Bp += (size_t)8 * N;
        As[aCol + 0][aRow] = a4.x;
        As[aCol + 1][aRow] = a4.y;
        As[aCol + 2][aRow] = a4.z;
        As[aCol + 3][aRow] = a4.w;
        *(float4*)&Bs[bRow][bCol] = b4;
        __syncthreads();
#pragma unroll
        for (int kk = 0; kk < 8; kk++) {
            float4 a0 = *(const float4*)&As[kk][ty];
            float4 a1 = *(const float4*)&As[kk][ty + 4];
            float4 b0 = *(const float4*)&Bs[kk][tx];
            float4 b1 = *(const float4*)&Bs[kk][tx + 4];
            float ra[8] = {a0.x, a0.y, a0.z, a0.w, a1.x, a1.y, a1.z, a1.w};
            float rb[8] = {b0.x, b0.y, b0.z, b0.w, b1.x, b1.y, b1.z, b1.w};
#pragma unroll
            for (int i = 0; i < 8; i++)
#pragma unroll
                for (int j = 0; j < 8; j++)
                    acc[i][j] = fmaf(ra[i], rb[j], acc[i][j]);
        }
        __syncthreads();
    }

    int row0 = bm * 128 + ty, col0 = bn * 128 + tx;
#pragma unroll
    for (int i = 0; i < 8; i++) {
        int row = row0 + i;
        size_t base = (size_t)row * N + col0;
#pragma unroll
        for (int j = 0; j < 8; j++) {
            float vv = acc[i][j];
            if (bias) vv += bias[col0 + j];
            if (gelu) vv = 0.5f * vv * (1.0f + erff(vv * 0.70710678118654752f));
            if (res)  vv += res[base + j];
            C[base + j] = vv;
        }
    }
}

__global__ __launch_bounds__(256, 2) void sgemm_kernel(const float* A, const float* Bw,
                                                       const float* bias, const float* res,
                                                       float* C, int M, int N, int K, int gelu) {
    gemm_body(A, Bw, bias, res, C, M, N, K, gelu);
}

// fused QKV: blockIdx.z selects which projection (384 blocks -> better SM fill)
__global__ __launch_bounds__(256, 2) void sgemm_qkv_kernel(const float* A,
                                                           const float* Wq, const float* Wk, const float* Wv,
                                                           const float* bq, const float* bk, const float* bv,
                                                           float* Q, float* Ko, float* Vo) {
    const float* W; const float* bi; float* C;
    if (blockIdx.z == 0)      { W = Wq; bi = bq; C = Q;  }
    else if (blockIdx.z == 1) { W = Wk; bi = bk; C = Ko; }
    else                      { W = Wv; bi = bv; C = Vo; }
    gemm_body(A, W, bi, nullptr, C, TT, DD, DD, 0);
}

// ---------------- causal attention: one block per (b, h, q) ----------------
__global__ __launch_bounds__(256) void attn_kernel(const float* __restrict__ Q,
                                                   const float* __restrict__ Kc,
                                                   const float* __restrict__ Vc,
                                                   float* __restrict__ O) {
    int qi = blockIdx.x, h = blockIdx.y, b = blockIdx.z;
    int tid = threadIdx.x;
    __shared__ float sc[SS];
    __shared__ float qs[HD];
    __shared__ float red[8];
    __shared__ float pv[4][HD];
    __shared__ float s_m, s_s;

    const float* qrow = Q + (size_t)(b * SS + qi) * DD + h * HD;
    if (tid < HD) qs[tid] = qrow[tid];
    __syncthreads();

    int n = qi + 1;
    float lmax = -1e30f;
    for (int j = tid; j < n; j += 256) {
        const float* kr = Kc + (size_t)(b * SS + j) * DD + h * HD;
        float d = 0.f;
#pragma unroll
        for (int t4 = 0; t4 < 16; t4++) {
            float4 k4 = *(const float4*)(kr + t4 * 4);
            d += qs[t4 * 4 + 0] * k4.x + qs[t4 * 4 + 1] * k4.y +
                 qs[t4 * 4 + 2] * k4.z + qs[t4 * 4 + 3] * k4.w;
        }
        d *= 0.125f;  // 1/sqrt(64)
        sc[j] = d;
        lmax = fmaxf(lmax, d);
    }
    for (int o = 16; o; o >>= 1) lmax = fmaxf(lmax, __shfl_xor_sync(0xffffffffu, lmax, o));
    if (!(tid & 31)) red[tid >> 5] = lmax;
    __syncthreads();
    if (tid == 0) {
        float m = red[0];
        for (int i = 1; i < 8; i++) m = fmaxf(m, red[i]);
        s_m = m;
    }
    __syncthreads();
    float m = s_m;
    float lsum = 0.f;
    for (int j = tid; j < n; j += 256) {
        float e = __expf(sc[j] - m);
        sc[j] = e;
        lsum += e;
    }
    for (int o = 16; o; o >>= 1) lsum += __shfl_xor_sync(0xffffffffu, lsum, o);
    __syncthreads();               // red reuse + sc visibility
    if (!(tid & 31)) red[tid >> 5] = lsum;
    __syncthreads();
    if (tid == 0) {
        float s = 0.f;
        for (int i = 0; i < 8; i++) s += red[i];
        s_s = s;
    }
    __syncthreads();
    float inv = 1.0f / s_s;

    int d = tid & 63, grp = tid >> 6;       // 4 groups x 64 dims
    float acc = 0.f;
    for (int j = grp; j < n; j += 4)
        acc += sc[j] * Vc[(size_t)(b * SS + j) * DD + h * HD + d];
    pv[grp][d] = acc;
    __syncthreads();
    if (tid < HD)
        O[(size_t)(b * SS + qi) * DD + h * HD + tid] =
            (pv[0][tid] + pv[1][tid] + pv[2][tid] + pv[3][tid]) * inv;
}

// ---------------- launch ----------------
extern "C" void kernel_launch(void* const* d_in, const int* in_sizes, int n_in,
                              void* d_out, int out_size) {
    const float* emb  = (const float*)d_in[0];
    const float* Wq   = (const float*)d_in[1];
    const float* bq   = (const float*)d_in[2];
    const float* Wk   = (const float*)d_in[3];
    const float* bk   = (const float*)d_in[4];
    const float* Wv   = (const float*)d_in[5];
    const float* bv   = (const float*)d_in[6];
    const float* Wo   = (const float*)d_in[7];
    const float* bo   = (const float*)d_in[8];
    const float* ln1g = (const float*)d_in[9];
    const float* ln1b = (const float*)d_in[10];
    const float* W1   = (const float*)d_in[11];
    const float* b1   = (const float*)d_in[12];
    const float* W2   = (const float*)d_in[13];
    const float* b2   = (const float*)d_in[14];
    const float* ln2g = (const float*)d_in[15];
    const float* ln2b = (const float*)d_in[16];
    const float* lnfg = (const float*)d_in[17];
    const float* lnfb = (const float*)d_in[18];
    const float* Wout = (const float*)d_in[19];
    const int*   ids  = (const int*)d_in[20];

    float *x, *h, *q, *k, *v, *at, *ff;
    cudaGetSymbolAddress((void**)&x,  g_x);
    cudaGetSymbolAddress((void**)&h,  g_h);
    cudaGetSymbolAddress((void**)&q,  g_q);
    cudaGetSymbolAddress((void**)&k,  g_k);
    cudaGetSymbolAddress((void**)&v,  g_v);
    cudaGetSymbolAddress((void**)&at, g_at);
    cudaGetSymbolAddress((void**)&ff, g_ff);

    embed_kernel<<<(TT * DD) / 256, 256>>>(emb, ids, x);

    dim3 gN1(DD / 128, TT / 128);        // (8, 16)
    dim3 gQKV(DD / 128, TT / 128, 3);    // (8, 16, 3)
    dim3 gFF1(FFD / 128, TT / 128);      // (32, 16)
    dim3 gOut(VV / 128, TT / 128);       // (250, 16)
    dim3 gAttn(SS, HH, BB);

    for (int l = 0; l < LL; l++) {
        size_t woff = (size_t)l * DD * DD;
        ln_kernel<<<TT, 256>>>(x, ln1g + l * DD, ln1b + l * DD, h);
        sgemm_qkv_kernel<<<gQKV, 256>>>(h, Wq + woff, Wk + woff, Wv + woff,
                                        bq + l * DD, bk + l * DD, bv + l * DD,
                                        q, k, v);
        attn_kernel<<<gAttn, 256>>>(q, k, v, at);
        // x = x + attn @ Wo + bo   (in-place residual: each element owned by one thread)
        sgemm_kernel<<<gN1, 256>>>(at, Wo + woff, bo + l * DD, x, x, TT, DD, DD, 0);
        ln_kernel<<<TT, 256>>>(x, ln2g + l * DD, ln2b + l * DD, h);
        // ff = gelu(h @ W1 + b1)
        sgemm_kernel<<<gFF1, 256>>>(h, W1 + (size_t)l * DD * FFD, b1 + l * FFD,
                                    nullptr, ff, TT, FFD, DD, 1);
        // x = x + ff @ W2 + b2
        sgemm_kernel<<<gN1, 256>>>(ff, W2 + (size_t)l * FFD * DD, b2 + l * DD,
                                   x, x, TT, DD, FFD, 0);
    }
    ln_kernel<<<TT, 256>>>(x, lnfg, lnfb, h);
    // logits = h @ Wout  (no bias)
    sgemm_kernel<<<gOut, 256>>>(h, Wout, nullptr, nullptr, (float*)d_out,
                                TT, VV, DD, 0);
}

// round 7
// speedup vs baseline: 2.0901x; 2.0864x over previous
#include <cuda_runtime.h>
#include <cuda_bf16.h>
#include <math.h>
#include <stdint.h>

#define TT 2048      // B*S tokens
#define DD 1024      // model dim
#define FFD 4096     // ff dim
#define VV 32000     // vocab
#define HH 16        // heads
#define HD 64        // head dim
#define LL 6         // layers
#define SS 1024      // seq len
#define BB 2         // batch

// ---------------- scratch (no allocation allowed) ----------------
__device__ float g_x[TT * DD];
__device__ float g_h[TT * DD];
__device__ float g_q[TT * DD];
__device__ float g_k[TT * DD];
__device__ float g_v[TT * DD];
__device__ float g_at[TT * DD];
__device__ float g_ff[TT * FFD];

// ---------------- embedding + sinusoidal positional encoding ----------------
__global__ void embed_kernel(const float* __restrict__ emb,
                             const int* __restrict__ ids,
                             float* __restrict__ x) {
    int idx = blockIdx.x * 256 + threadIdx.x;
    if (idx >= TT * DD) return;
    int t = idx >> 10;
    int d = idx & (DD - 1);
    int pos = t & (SS - 1);
    float val = emb[ids[t] * DD + d] * 32.0f;
    float ang = (float)pos * expf((float)(d & ~1) * (-9.210340371976184f / 1024.0f));
    val += (d & 1) ? cosf(ang) : sinf(ang);
    x[idx] = val;
}

// ---------------- layernorm ----------------
__global__ __launch_bounds__(256) void ln_kernel(const float* __restrict__ x,
                                                 const float* __restrict__ g,
                                                 const float* __restrict__ bta,
                                                 float* __restrict__ out) {
    int row = blockIdx.x;
    const float* xr = x + (size_t)row * DD;
    float s1 = 0.f, s2 = 0.f;
    for (int i = threadIdx.x; i < DD; i += 256) {
        float v = xr[i];
        s1 += v;
        s2 = fmaf(v, v, s2);
    }
    for (int o = 16; o; o >>= 1) {
        s1 += __shfl_xor_sync(0xffffffffu, s1, o);
        s2 += __shfl_xor_sync(0xffffffffu, s2, o);
    }
    __shared__ float r1[8], r2[8];
    __shared__ float smean, srstd;
    int w = threadIdx.x >> 5, lane = threadIdx.x & 31;
    if (lane == 0) { r1[w] = s1; r2[w] = s2; }
    __syncthreads();
    if (threadIdx.x == 0) {
        float t1 = 0.f, t2 = 0.f;
        for (int i = 0; i < 8; i++) { t1 += r1[i]; t2 += r2[i]; }
        float mean = t1 * (1.0f / DD);
        float var  = t2 * (1.0f / DD) - mean * mean;
        smean = mean;
        srstd = rsqrtf(var + 1e-5f);
    }
    __syncthreads();
    float mean = smean, rstd = srstd;
    for (int i = threadIdx.x; i < DD; i += 256)
        out[(size_t)row * DD + i] = (xr[i] - mean) * rstd * g[i] + bta[i];
}

// ---------------- tf32 helpers ----------------
__device__ __forceinline__ void split_tf32(float f, uint32_t& hi, uint32_t& lo) {
    asm("cvt.rna.tf32.f32 %0, %1;" : "=r"(hi) : "f"(f));
    float r = f - __uint_as_float(hi);
    asm("cvt.rna.tf32.f32 %0, %1;" : "=r"(lo) : "f"(r));
}

__device__ __forceinline__ void mma_tf32(float* c, const uint32_t* a, const uint32_t* b) {
    asm volatile(
        "mma.sync.aligned.m16n8k8.row.col.f32.tf32.tf32.f32 "
        "{%0,%1,%2,%3}, {%4,%5,%6,%7}, {%8,%9}, {%0,%1,%2,%3};\n"
        : "+f"(c[0]), "+f"(c[1]), "+f"(c[2]), "+f"(c[3])
        : "r"(a[0]), "r"(a[1]), "r"(a[2]), "r"(a[3]), "r"(b[0]), "r"(b[1]));
}

// ---------------- 3xTF32 tensor-core GEMM: 128x128x32 tiles ----------------
// C[M,N] = A[M,K] @ B[K,N] (+bias)(gelu?)(+res). M%128==0, N%128==0, K%32==0.
#define AST 136   // As row stride (BM=128 + 8): banks 8k+m conflict-free
#define BST 136   // Bs row stride (BN=128 + 8)

__device__ __forceinline__ void gemm_body_tc(const float* __restrict__ A,
                                             const float* __restrict__ Bw,
                                             const float* __restrict__ bias,
                                             const float* __restrict__ res,
                                             float* __restrict__ C,
                                             int M, int N, int K, int gelu) {
    __shared__ float As_s[32 * AST];   // [k][m]
    __shared__ float Bs_s[32 * BST];   // [k][n]
    int t = threadIdx.x;
    int bm = blockIdx.y, bn = blockIdx.x;
    int w = t >> 5, lane = t & 31;
    int wm = w >> 2, wn = w & 3;                 // warps: 2(m) x 4(n)
    int m_base = wm * 64, n_base = wn * 32;
    int gid = lane >> 2, tig = lane & 3;

    // A global map: m = t&127 (fixed), k4 = t>>7 + 2i
    int am = t & 127;
    int ak4 = t >> 7;
    const float* Arow = A + (size_t)(bm * 128 + am) * K;
    // B global map: n4 = t&31, kr = t>>5 + 8i
    int bn4 = t & 31;
    int bkr = t >> 5;
    const float* Bcol = Bw + bn * 128 + bn4 * 4;

    float acc[4][4][4];
#pragma unroll
    for (int mf = 0; mf < 4; mf++)
#pragma unroll
        for (int nf = 0; nf < 4; nf++)
#pragma unroll
            for (int r = 0; r < 4; r++) acc[mf][nf][r] = 0.f;

    int ntiles = K >> 5;
    float4 ra[4], rb[4];

    // prefetch tile 0
#pragma unroll
    for (int i = 0; i < 4; i++) {
        ra[i] = *(const float4*)(Arow + (ak4 + 2 * i) * 4);
        rb[i] = *(const float4*)(Bcol + (size_t)(bkr + 8 * i) * N);
    }
#pragma unroll
    for (int i = 0; i < 4; i++) {
        int k4 = ak4 + 2 * i;
        As_s[(k4 * 4 + 0) * AST + am] = ra[i].x;
        As_s[(k4 * 4 + 1) * AST + am] = ra[i].y;
        As_s[(k4 * 4 + 2) * AST + am] = ra[i].z;
        As_s[(k4 * 4 + 3) * AST + am] = ra[i].w;
        *(float4*)&Bs_s[(bkr + 8 * i) * BST + bn4 * 4] = rb[i];
    }
    __syncthreads();

    for (int tt = 0; tt < ntiles; tt++) {
        if (tt + 1 < ntiles) {
            int k0 = (tt + 1) << 5;
#pragma unroll
            for (int i = 0; i < 4; i++) {
                ra[i] = *(const float4*)(Arow + k0 + (ak4 + 2 * i) * 4);
                rb[i] = *(const float4*)(Bcol + (size_t)(k0 + bkr + 8 * i) * N);
            }
        }
        // compute on smem tile
#pragma unroll
        for (int ks = 0; ks < 32; ks += 8) {
            uint32_t bhi[4][2], blo[4][2];
#pragma unroll
            for (int nf = 0; nf < 4; nf++) {
                float b0 = Bs_s[(ks + tig) * BST + n_base + nf * 8 + gid];
                float b1 = Bs_s[(ks + tig + 4) * BST + n_base + nf * 8 + gid];
                split_tf32(b0, bhi[nf][0], blo[nf][0]);
                split_tf32(b1, bhi[nf][1], blo[nf][1]);
            }
#pragma unroll
            for (int mf = 0; mf < 4; mf++) {
                int mc = m_base + mf * 16 + gid;
                float a0 = As_s[(ks + tig) * AST + mc];
                float a1 = As_s[(ks + tig) * AST + mc + 8];
                float a2 = As_s[(ks + tig + 4) * AST + mc];
                float a3 = As_s[(ks + tig + 4) * AST + mc + 8];
                uint32_t ahi[4], alo[4];
                split_tf32(a0, ahi[0], alo[0]);
                split_tf32(a1, ahi[1], alo[1]);
                split_tf32(a2, ahi[2], alo[2]);
                split_tf32(a3, ahi[3], alo[3]);
#pragma unroll
                for (int nf = 0; nf < 4; nf++) {
                    mma_tf32(acc[mf][nf], ahi, bhi[nf]);
                    mma_tf32(acc[mf][nf], ahi, blo[nf]);
                    mma_tf32(acc[mf][nf], alo, bhi[nf]);
                }
            }
        }
        __syncthreads();
        if (tt + 1 < ntiles) {
#pragma unroll
            for (int i = 0; i < 4; i++) {
                int k4 = ak4 + 2 * i;
                As_s[(k4 * 4 + 0) * AST + am] = ra[i].x;
                As_s[(k4 * 4 + 1) * AST + am] = ra[i].y;
                As_s[(k4 * 4 + 2) * AST + am] = ra[i].z;
                As_s[(k4 * 4 + 3) * AST + am] = ra[i].w;
                *(float4*)&Bs_s[(bkr + 8 * i) * BST + bn4 * 4] = rb[i];
            }
            __syncthreads();
        }
    }

    // epilogue
#pragma unroll
    for (int mf = 0; mf < 4; mf++) {
        int row0 = bm * 128 + m_base + mf * 16 + gid;
#pragma unroll
        for (int nf = 0; nf < 4; nf++) {
            int col = bn * 128 + n_base + nf * 8 + tig * 2;
#pragma unroll
            for (int r = 0; r < 4; r++) {
                int row = row0 + ((r >> 1) ? 8 : 0);
                int cc = col + (r & 1);
                float vv = acc[mf][nf][r];
                if (bias) vv += bias[cc];
                if (gelu) vv = 0.5f * vv * (1.0f + erff(vv * 0.70710678118654752f));
                size_t o = (size_t)row * N + cc;
                if (res) vv += res[o];
                C[o] = vv;
            }
        }
    }
}

__global__ __launch_bounds__(256) void sgemm_kernel(const float* A, const float* Bw,
                                                    const float* bias, const float* res,
                                                    float* C, int M, int N, int K, int gelu) {
    gemm_body_tc(A, Bw, bias, res, C, M, N, K, gelu);
}

__global__ __launch_bounds__(256) void sgemm_qkv_kernel(const float* A,
                                                        const float* Wq, const float* Wk, const float* Wv,
                                                        const float* bq, const float* bk, const float* bv,
                                                        float* Q, float* Ko, float* Vo) {
    const float* W; const float* bi; float* C;
    if (blockIdx.z == 0)      { W = Wq; bi = bq; C = Q;  }
    else if (blockIdx.z == 1) { W = Wk; bi = bk; C = Ko; }
    else                      { W = Wv; bi = bv; C = Vo; }
    gemm_body_tc(A, W, bi, nullptr, C, TT, DD, DD, 0);
}

// ---------------- flash attention: block = (qtile64, h, b), 256 threads ----------------
// smem: Qt[d][q] 64x68, Kt[d][k] 64x68, Vs[k][d] 64x68, Ps[k][q] 64x68 + state
#define FST 68
__global__ __launch_bounds__(256) void flash_attn_kernel(const float* __restrict__ Q,
                                                         const float* __restrict__ Kc,
                                                         const float* __restrict__ Vc,
                                                         float* __restrict__ O) {
    extern __shared__ float sb[];
    float* Qt = sb;                     // [64][FST]  (d-major, scaled)
    float* Kt = Qt + 64 * FST;          // [64][FST]  (d-major)
    float* Vs = Kt + 64 * FST;          // [64][FST]  (k-major)
    float* Ps = Vs + 64 * FST;          // [64][FST]  (k-major: Ps[k][q])
    float* smx = Ps + 64 * FST;         // [64] running max
    float* slx = smx + 64;              // [64] running sum
    float* sfx = slx + 64;              // [64] rescale factor

    int qt = blockIdx.x, h = blockIdx.y, b = blockIdx.z;
    int t = threadIdx.x;

    // load Q tile transposed, scaled by 1/sqrt(64)
    {
        int q = t & 63, d4 = t >> 6;   // d4 in 0..3, +4 per iter
#pragma unroll
        for (int i = 0; i < 4; i++) {
            int dd4 = d4 + 4 * i;
            float4 f = *(const float4*)(Q + (size_t)(b * SS + qt * 64 + q) * DD + h * HD + dd4 * 4);
            Qt[(dd4 * 4 + 0) * FST + q] = f.x * 0.125f;
            Qt[(dd4 * 4 + 1) * FST + q] = f.y * 0.125f;
            Qt[(dd4 * 4 + 2) * FST + q] = f.z * 0.125f;
            Qt[(dd4 * 4 + 3) * FST + q] = f.w * 0.125f;
        }
    }
    if (t < 64) { smx[t] = -1e30f; slx[t] = 0.f; }

    float o[4][4];
#pragma unroll
    for (int i = 0; i < 4; i++)
#pragma unroll
        for (int j = 0; j < 4; j++) o[i][j] = 0.f;

    int qg = t & 15, kg = t >> 4;      // S-compute mapping (4q x 4k per thread)
    int qg2 = t >> 4, dg = t & 15;     // PV mapping (4q x 4d per thread)

    __syncthreads();

    for (int kt = 0; kt <= qt; kt++) {
        // load K tile transposed + V tile natural
        {
            int k = t & 63, d4 = t >> 6;
#pragma unroll
            for (int i = 0; i < 4; i++) {
                int dd4 = d4 + 4 * i;
                float4 f = *(const float4*)(Kc + (size_t)(b * SS + kt * 64 + k) * DD + h * HD + dd4 * 4);
                Kt[(dd4 * 4 + 0) * FST + k] = f.x;
                Kt[(dd4 * 4 + 1) * FST + k] = f.y;
                Kt[(dd4 * 4 + 2) * FST + k] = f.z;
                Kt[(dd4 * 4 + 3) * FST + k] = f.w;
            }
            int kv = t >> 4, dv4 = t & 15;
#pragma unroll
            for (int i = 0; i < 4; i++) {
                int kk = kv + 16 * i;
                float4 f = *(const float4*)(Vc + (size_t)(b * SS + kt * 64 + kk) * DD + h * HD + dv4 * 4);
                *(float4*)&Vs[kk * FST + dv4 * 4] = f;
            }
        }
        __syncthreads();

        // S = Q K^T  (4x4 per thread over d)
        float s[4][4];
#pragma unroll
        for (int i = 0; i < 4; i++)
#pragma unroll
            for (int j = 0; j < 4; j++) s[i][j] = 0.f;
        for (int d = 0; d < 64; d++) {
            float4 q4 = *(const float4*)&Qt[d * FST + qg * 4];
            float4 k4 = *(const float4*)&Kt[d * FST + kg * 4];
            float qa[4] = {q4.x, q4.y, q4.z, q4.w};
            float ka[4] = {k4.x, k4.y, k4.z, k4.w};
#pragma unroll
            for (int i = 0; i < 4; i++)
#pragma unroll
                for (int j = 0; j < 4; j++)
                    s[i][j] = fmaf(qa[i], ka[j], s[i][j]);
        }
        if (kt == qt) {   // causal mask on diagonal tile
#pragma unroll
            for (int i = 0; i < 4; i++)
#pragma unroll
                for (int j = 0; j < 4; j++)
                    if (kg * 4 + j > qg * 4 + i) s[i][j] = -1e30f;
        }
        // store S^T to Ps[k][q]
#pragma unroll
        for (int j = 0; j < 4; j++)
#pragma unroll
            for (int i = 0; i < 4; i++)
                Ps[(kg * 4 + j) * FST + qg * 4 + i] = s[i][j];
        __syncthreads();

        // online softmax per q column (threads 0..63)
        if (t < 64) {
            int q = t;
            float m_old = smx[q];
            float tm = -1e30f;
            for (int k = 0; k < 64; k++) tm = fmaxf(tm, Ps[k * FST + q]);
            float mn = fmaxf(m_old, tm);
            float f = __expf(m_old - mn);
            float ssum = 0.f;
            for (int k = 0; k < 64; k++) {
                float p = __expf(Ps[k * FST + q] - mn);
                Ps[k * FST + q] = p;
                ssum += p;
            }
            smx[q] = mn;
            slx[q] = slx[q] * f + ssum;
            sfx[q] = f;
        }
        __syncthreads();

        // rescale O and accumulate P V
        {
            float f0 = sfx[qg2 * 4 + 0], f1 = sfx[qg2 * 4 + 1];
            float f2 = sfx[qg2 * 4 + 2], f3 = sfx[qg2 * 4 + 3];
#pragma unroll
            for (int j = 0; j < 4; j++) {
                o[0][j] *= f0; o[1][j] *= f1; o[2][j] *= f2; o[3][j] *= f3;
            }
        }
        for (int k = 0; k < 64; k++) {
            float4 p4 = *(const float4*)&Ps[k * FST + qg2 * 4];
            float4 v4 = *(const float4*)&Vs[k * FST + dg * 4];
            float pa[4] = {p4.x, p4.y, p4.z, p4.w};
            float va[4] = {v4.x, v4.y, v4.z, v4.w};
#pragma unroll
            for (int i = 0; i < 4; i++)
#pragma unroll
                for (int j = 0; j < 4; j++)
                    o[i][j] = fmaf(pa[i], va[j], o[i][j]);
        }
        __syncthreads();
    }

    // normalize + write
#pragma unroll
    for (int i = 0; i < 4; i++) {
        int q = qg2 * 4 + i;
        float inv = 1.0f / slx[q];
        float4 f;
        f.x = o[i][0] * inv; f.y = o[i][1] * inv;
        f.z = o[i][2] * inv; f.w = o[i][3] * inv;
        *(float4*)(O + (size_t)(b * SS + qt * 64 + q) * DD + h * HD + dg * 4) = f;
    }
}

// ---------------- launch ----------------
extern "C" void kernel_launch(void* const* d_in, const int* in_sizes, int n_in,
                              void* d_out, int out_size) {
    const float* emb  = (const float*)d_in[0];
    const float* Wq   = (const float*)d_in[1];
    const float* bq   = (const float*)d_in[2];
    const float* Wk   = (const float*)d_in[3];
    const float* bk   = (const float*)d_in[4];
    const float* Wv   = (const float*)d_in[5];
    const float* bv   = (const float*)d_in[6];
    const float* Wo   = (const float*)d_in[7];
    const float* bo   = (const float*)d_in[8];
    const float* ln1g = (const float*)d_in[9];
    const float* ln1b = (const float*)d_in[10];
    const float* W1   = (const float*)d_in[11];
    const float* b1   = (const float*)d_in[12];
    const float* W2   = (const float*)d_in[13];
    const float* b2   = (const float*)d_in[14];
    const float* ln2g = (const float*)d_in[15];
    const float* ln2b = (const float*)d_in[16];
    const float* lnfg = (const float*)d_in[17];
    const float* lnfb = (const float*)d_in[18];
    const float* Wout = (const float*)d_in[19];
    const int*   ids  = (const int*)d_in[20];

    float *x, *h, *q, *k, *v, *at, *ff;
    cudaGetSymbolAddress((void**)&x,  g_x);
    cudaGetSymbolAddress((void**)&h,  g_h);
    cudaGetSymbolAddress((void**)&q,  g_q);
    cudaGetSymbolAddress((void**)&k,  g_k);
    cudaGetSymbolAddress((void**)&v,  g_v);
    cudaGetSymbolAddress((void**)&at, g_at);
    cudaGetSymbolAddress((void**)&ff, g_ff);

    static int attr_set = 0;
    const int flash_smem = (4 * 64 * FST + 3 * 64) * 4;
    if (!attr_set) {
        cudaFuncSetAttribute(flash_attn_kernel,
                             cudaFuncAttributeMaxDynamicSharedMemorySize, flash_smem);
        attr_set = 1;
    }

    embed_kernel<<<(TT * DD) / 256, 256>>>(emb, ids, x);

    dim3 gN1(DD / 128, TT / 128);        // (8, 16)
    dim3 gQKV(DD / 128, TT / 128, 3);    // (8, 16, 3)
    dim3 gFF1(FFD / 128, TT / 128);      // (32, 16)
    dim3 gOut(VV / 128, TT / 128);       // (250, 16)
    dim3 gAttn(SS / 64, HH, BB);         // (16, 16, 2)

    for (int l = 0; l < LL; l++) {
        size_t woff = (size_t)l * DD * DD;
        ln_kernel<<<TT, 256>>>(x, ln1g + l * DD, ln1b + l * DD, h);
        sgemm_qkv_kernel<<<gQKV, 256>>>(h, Wq + woff, Wk + woff, Wv + woff,
                                        bq + l * DD, bk + l * DD, bv + l * DD,
                                        q, k, v);
        flash_attn_kernel<<<gAttn, 256, flash_smem>>>(q, k, v, at);
        sgemm_kernel<<<gN1, 256>>>(at, Wo + woff, bo + l * DD, x, x, TT, DD, DD, 0);
        ln_kernel<<<TT, 256>>>(x, ln2g + l * DD, ln2b + l * DD, h);
        sgemm_kernel<<<gFF1, 256>>>(h, W1 + (size_t)l * DD * FFD, b1 + l * FFD,
                                    nullptr, ff, TT, FFD, DD, 1);
        sgemm_kernel<<<gN1, 256>>>(ff, W2 + (size_t)l * FFD * DD, b2 + l * DD,
                                   x, x, TT, DD, FFD, 0);
    }
    ln_kernel<<<TT, 256>>>(x, lnfg, lnfb, h);
    sgemm_kernel<<<gOut, 256>>>(h, Wout, nullptr, nullptr, (float*)d_out,
                                TT, VV, DD, 0);
}